// round 10
// baseline (speedup 1.0000x reference)
#include <cuda_runtime.h>
#include <cuda_fp16.h>
#include <cstdint>

#define NROW 8192
#define FDIM 512
#define LDBM 576          // B row stride (halves): 512 feats + 8 den + pad to 1152B

// ------------------------- scratch -------------------------
__device__ __half   g_X16[(size_t)NROW * FDIM];
__device__ __half   g_Wt [(size_t)FDIM * FDIM];   // Wt[f][c], c=h*64+o
__device__ __half   g_A16[(size_t)NROW * NROW];   // A in fp16 (exact 0/1)
__device__ float    g_WX [(size_t)NROW * FDIM];
__device__ float    g_s2 [8 * NROW];
__device__ float    g_mx [8];
__device__ unsigned g_cnt;
__device__ __half   g_B  [(size_t)NROW * LDBM];   // B[j][c]: w*WX (c<512), w (512..519)

// ------------------------- templated mma.sync GEMM (BK=64, 3-stage) ---------
// C[m0+128, n0+128] = A[M,KLEN] @ B[k][n], A fp16 K-major, B row-major (LDBg).
// DEN:  8 extra B cols (512..519) accumulated by wn==0 warps; epilogue writes
//       relu(acc/den) straight to C (stride 512).
// S2:   epilogue accumulates s2[h,row] = dot(C_row_tile, a2) via atomicAdd,
//       and the LAST CTA computes per-head maxima into g_mx.
template<int KLEN, int LDBg, bool DEN, bool S2>
__global__ __launch_bounds__(256, 2)
void k_mm(const __half* __restrict__ Ag, const __half* __restrict__ Bg,
          float* __restrict__ Cg, const float* __restrict__ attn)
{
    constexpr int BK     = 64;
    constexpr int NKT    = KLEN / BK;              // 128 main, 8 WX
    constexpr int ASTR   = 72;                     // halves; 4r bank pattern
    constexpr int BSTR   = DEN ? 152 : 136;        // halves; 12r / 4r bank pattern
    constexpr int NI     = 4;
    constexpr int CPR    = 16 + (DEN ? 1 : 0);     // 16B chunks per B row
    constexpr int A16_SZ = 128 * ASTR * 2;         // 18432
    constexpr int B_SZ   = BK * BSTR * 2;
    constexpr int OFF_B  = 3 * A16_SZ;

    extern __shared__ char smem[];
    const uint32_t sbase = (uint32_t)__cvta_generic_to_shared(smem);

    const int tid = threadIdx.x;
    const int wid = tid >> 5, lane = tid & 31;
    const int wm = wid & 1, wn = wid >> 1;
    const int lr = lane & 15, lc = (lane >> 4) * 8;
    const int l4 = lane & 3,  lg = lane >> 2;
    const int m0 = blockIdx.y * 128, n0 = blockIdx.x * 128;

    float acc[4][NI][4];
    #pragma unroll
    for (int a = 0; a < 4; a++)
        #pragma unroll
        for (int b = 0; b < NI; b++)
            #pragma unroll
            for (int c = 0; c < 4; c++) acc[a][b][c] = 0.f;
    float accD[4][4];
    if (DEN) {
        #pragma unroll
        for (int a = 0; a < 4; a++)
            #pragma unroll
            for (int c = 0; c < 4; c++) accD[a][c] = 0.f;
    }

    auto load_stage = [&](int kt) {
        const int s = kt % 3;
        uint32_t sa = sbase + s * A16_SZ;
        const __half* g0 = Ag + (size_t)m0 * KLEN + (size_t)kt * BK;
        #pragma unroll
        for (int i = 0; i < 4; i++) {              // A: 128 rows x 8 chunks
            int ch = i * 256 + tid;
            int r = ch >> 3, c8 = ch & 7;
            asm volatile("cp.async.cg.shared.global [%0], [%1], 16;"
                         :: "r"(sa + r * (ASTR * 2) + c8 * 16),
                            "l"(g0 + (size_t)r * KLEN + c8 * 8));
        }
        uint32_t sb = sbase + OFF_B + s * B_SZ;
        const __half* gb = Bg + (size_t)kt * BK * LDBg;
        #pragma unroll
        for (int i = 0; i < (DEN ? 5 : 4); i++) {  // B: 64 rows x CPR chunks
            int ch = i * 256 + tid;
            if (!DEN || ch < 64 * CPR) {
                int r, cc;
                if (DEN) { r = ch / CPR; cc = ch % CPR; }
                else     { r = ch >> 4;  cc = ch & 15; }
                int gcol = (cc < 16) ? (n0 + cc * 8) : 512;
                asm volatile("cp.async.cg.shared.global [%0], [%1], 16;"
                             :: "r"(sb + r * (BSTR * 2) + cc * 16),
                                "l"(gb + (size_t)r * LDBg + gcol));
            }
        }
    };

    auto compute = [&](int kt) {
        const int s = kt % 3;
        const uint32_t a16b = sbase + s * A16_SZ;
        const uint32_t bb   = sbase + OFF_B + s * B_SZ;
        #pragma unroll
        for (int ks = 0; ks < 4; ks++) {           // BK=64 -> 4 k16 sections
            uint32_t af[4][4], bf[NI][2], dn[2];
            #pragma unroll
            for (int mi = 0; mi < 4; mi++) {
                uint32_t ad = a16b + ((wm * 64 + mi * 16 + lr) * ASTR + ks * 16 + lc) * 2;
                asm volatile("ldmatrix.sync.aligned.m8n8.x4.shared.b16 {%0,%1,%2,%3}, [%4];"
                             : "=r"(af[mi][0]), "=r"(af[mi][1]),
                               "=r"(af[mi][2]), "=r"(af[mi][3]) : "r"(ad));
            }
            #pragma unroll
            for (int nj = 0; nj < NI / 2; nj++) {
                uint32_t bd_ = bb + ((ks * 16 + lr) * BSTR + wn * 32 + nj * 16 + lc) * 2;
                asm volatile("ldmatrix.sync.aligned.m8n8.x4.trans.shared.b16 {%0,%1,%2,%3}, [%4];"
                             : "=r"(bf[nj * 2][0]), "=r"(bf[nj * 2][1]),
                               "=r"(bf[nj * 2 + 1][0]), "=r"(bf[nj * 2 + 1][1]) : "r"(bd_));
            }
            if (DEN && wn == 0) {
                uint32_t dd = bb + ((ks * 16 + lr) * BSTR + 128) * 2;
                asm volatile("ldmatrix.sync.aligned.m8n8.x2.trans.shared.b16 {%0,%1}, [%2];"
                             : "=r"(dn[0]), "=r"(dn[1]) : "r"(dd));
            }
            #pragma unroll
            for (int mi = 0; mi < 4; mi++) {
                #pragma unroll
                for (int ni = 0; ni < NI; ni++)
                    asm volatile(
                        "mma.sync.aligned.m16n8k16.row.col.f32.f16.f16.f32 "
                        "{%0,%1,%2,%3}, {%4,%5,%6,%7}, {%8,%9}, {%0,%1,%2,%3};"
                        : "+f"(acc[mi][ni][0]), "+f"(acc[mi][ni][1]),
                          "+f"(acc[mi][ni][2]), "+f"(acc[mi][ni][3])
                        : "r"(af[mi][0]), "r"(af[mi][1]), "r"(af[mi][2]), "r"(af[mi][3]),
                          "r"(bf[ni][0]), "r"(bf[ni][1]));
                if (DEN && wn == 0)
                    asm volatile(
                        "mma.sync.aligned.m16n8k16.row.col.f32.f16.f16.f32 "
                        "{%0,%1,%2,%3}, {%4,%5,%6,%7}, {%8,%9}, {%0,%1,%2,%3};"
                        : "+f"(accD[mi][0]), "+f"(accD[mi][1]),
                          "+f"(accD[mi][2]), "+f"(accD[mi][3])
                        : "r"(af[mi][0]), "r"(af[mi][1]), "r"(af[mi][2]), "r"(af[mi][3]),
                          "r"(dn[0]), "r"(dn[1]));
            }
        }
    };

    // ---- preamble: stages 0,1 committed; stage 0 resident ----
    load_stage(0); asm volatile("cp.async.commit_group;");
    load_stage(1); asm volatile("cp.async.commit_group;");
    asm volatile("cp.async.wait_group 1;");
    __syncthreads();

    // ---- mainloop: unconditional commits (empty groups at tail keep the
    //      wait_group accounting exact, no tail race) ----
    #pragma unroll 1
    for (int kt = 0; kt < NKT; kt++) {
        compute(kt);
        if (kt + 2 < NKT) load_stage(kt + 2);
        asm volatile("cp.async.commit_group;");
        asm volatile("cp.async.wait_group 1;");    // stage kt+1 resident
        __syncthreads();
    }

    // ---- epilogue (den scratch overlays stage 0 -- mainloop fully done) ----
    float* ds = (float*)smem;
    if (DEN) {
        if (wn == 0) {
            #pragma unroll
            for (int mi = 0; mi < 4; mi++) {
                int r = wm * 64 + mi * 16 + lg;
                ds[r * 8 + l4 * 2]           = 1.f / accD[mi][0];
                ds[r * 8 + l4 * 2 + 1]       = 1.f / accD[mi][1];
                ds[(r + 8) * 8 + l4 * 2]     = 1.f / accD[mi][2];
                ds[(r + 8) * 8 + l4 * 2 + 1] = 1.f / accD[mi][3];
            }
        }
        __syncthreads();
    }
    #pragma unroll
    for (int mi = 0; mi < 4; mi++) {
        int rl = wm * 64 + mi * 16 + lg;
        int rg = m0 + rl;
        #pragma unroll
        for (int ni = 0; ni < NI; ni++) {
            int c = n0 + wn * 32 + ni * 8 + l4 * 2;
            if (DEN) {
                int h = c >> 6;
                float d0 = ds[rl * 8 + h], d1 = ds[(rl + 8) * 8 + h];
                *reinterpret_cast<float2*>(&Cg[(size_t)rg * 512 + c]) =
                    make_float2(fmaxf(acc[mi][ni][0] * d0, 0.f),
                                fmaxf(acc[mi][ni][1] * d0, 0.f));
                *reinterpret_cast<float2*>(&Cg[(size_t)(rg + 8) * 512 + c]) =
                    make_float2(fmaxf(acc[mi][ni][2] * d1, 0.f),
                                fmaxf(acc[mi][ni][3] * d1, 0.f));
            } else {
                *reinterpret_cast<float2*>(&Cg[(size_t)rg * 512 + c]) =
                    make_float2(acc[mi][ni][0], acc[mi][ni][1]);
                *reinterpret_cast<float2*>(&Cg[(size_t)(rg + 8) * 512 + c]) =
                    make_float2(acc[mi][ni][2], acc[mi][ni][3]);
            }
        }
    }
    if (S2) {                                      // fused s2 partial dot
        const int hh = (n0 + wn * 32) >> 6;
        const float* a2 = attn + hh * 128 + 64;
        float a2v[NI][2];
        #pragma unroll
        for (int ni = 0; ni < NI; ni++) {
            int c = (wn * 32 + ni * 8 + l4 * 2) & 63;
            a2v[ni][0] = __ldg(a2 + c);
            a2v[ni][1] = __ldg(a2 + c + 1);
        }
        #pragma unroll
        for (int mi = 0; mi < 4; mi++) {
            float p0 = 0.f, p1 = 0.f;
            #pragma unroll
            for (int ni = 0; ni < NI; ni++) {
                p0 += acc[mi][ni][0] * a2v[ni][0] + acc[mi][ni][1] * a2v[ni][1];
                p1 += acc[mi][ni][2] * a2v[ni][0] + acc[mi][ni][3] * a2v[ni][1];
            }
            p0 += __shfl_xor_sync(0xFFFFFFFFu, p0, 1);
            p0 += __shfl_xor_sync(0xFFFFFFFFu, p0, 2);
            p1 += __shfl_xor_sync(0xFFFFFFFFu, p1, 1);
            p1 += __shfl_xor_sync(0xFFFFFFFFu, p1, 2);
            if (l4 == 0) {
                int r = m0 + wm * 64 + mi * 16 + lg;
                atomicAdd(&g_s2[hh * NROW + r], p0);
                atomicAdd(&g_s2[hh * NROW + r + 8], p1);
            }
        }
        __threadfence();
        __syncthreads();
        __shared__ unsigned sLast;
        if (tid == 0) sLast = (atomicAdd(&g_cnt, 1u) == 255u) ? 1u : 0u;
        __syncthreads();
        if (sLast) {
            __threadfence();
            const float4* p = reinterpret_cast<const float4*>(&g_s2[wid * NROW]);
            float m = -1e30f;
            #pragma unroll 4
            for (int i = lane; i < 2048; i += 32) {
                float4 v = __ldg(p + i);
                m = fmaxf(fmaxf(m, fmaxf(v.x, v.y)), fmaxf(v.z, v.w));
            }
            #pragma unroll
            for (int off = 16; off > 0; off >>= 1)
                m = fmaxf(m, __shfl_xor_sync(0xFFFFFFFFu, m, off));
            if (lane == 0) g_mx[wid] = m;
        }
    }
}

// ------------------------- prep kernel (all DRAM passes fused) --------------
__global__ void k_prep(const float* __restrict__ X, const float* __restrict__ A,
                       const float* __restrict__ kern) {
    int b = blockIdx.x;
    if (b < 4096) {                                // X -> fp16
        size_t i = (size_t)b * 256 + threadIdx.x;
        float4 v = reinterpret_cast<const float4*>(X)[i];
        __half2* d = reinterpret_cast<__half2*>(g_X16);
        d[2 * i]     = __floats2half2_rn(v.x, v.y);
        d[2 * i + 1] = __floats2half2_rn(v.z, v.w);
    } else if (b < 5120) {                         // kernels -> Wt[f][c]
        size_t i = (size_t)(b - 4096) * 256 + threadIdx.x;
        int f = (int)(i >> 9), c = (int)(i & 511);
        g_Wt[i] = __float2half_rn(kern[((size_t)(c >> 6) * 512 + f) * 64 + (c & 63)]);
    } else if (b < 5376) {                         // zero s2 (graph-replay safe)
        g_s2[(b - 5120) * 256 + threadIdx.x] = 0.f;
    } else if (b == 5376) {
        if (threadIdx.x == 0) g_cnt = 0u;
    } else {                                       // A -> fp16
        size_t i = (size_t)(b - 5377) * 256 + threadIdx.x;   // over 16M float4
        float4 v = reinterpret_cast<const float4*>(A)[i];
        __half2* d = reinterpret_cast<__half2*>(g_A16);
        d[2 * i]     = __floats2half2_rn(v.x, v.y);
        d[2 * i + 1] = __floats2half2_rn(v.z, v.w);
    }
}

__global__ void k_buildB() {                       // grid 8192, block 256
    int n = blockIdx.x;
    int c2 = threadIdx.x;                          // cols 2*c2, 2*c2+1 (same head)
    int h = c2 >> 5;
    float w = __expf(g_s2[h * NROW + n] - g_mx[h]);
    float2 wx = *reinterpret_cast<const float2*>(&g_WX[(size_t)n * FDIM + 2 * c2]);
    *reinterpret_cast<__half2*>(&g_B[(size_t)n * LDBM + 2 * c2]) =
        __floats2half2_rn(w * wx.x, w * wx.y);
    if (c2 < 8) {                                  // den col for head c2
        float wd = __expf(g_s2[c2 * NROW + n] - g_mx[c2]);
        g_B[(size_t)n * LDBM + 512 + c2] = __float2half_rn(wd);
    }
}

// ------------------------- launcher -------------------------
extern "C" void kernel_launch(void* const* d_in, const int* in_sizes, int n_in,
                              void* d_out, int out_size)
{
    const float* X    = (const float*)d_in[0];
    const float* A    = (const float*)d_in[1];
    const float* kern = (const float*)d_in[2];
    const float* attn = (const float*)d_in[3];
    float* out = (float*)d_out;

    void *pX16, *pWt, *pA16, *pWX, *pB;
    cudaGetSymbolAddress(&pX16, g_X16);
    cudaGetSymbolAddress(&pWt,  g_Wt);
    cudaGetSymbolAddress(&pA16, g_A16);
    cudaGetSymbolAddress(&pWX,  g_WX);
    cudaGetSymbolAddress(&pB,   g_B);

    constexpr int SM_WX   = 3 * 18432 + 3 * (64 * 136 * 2);   // 107520
    constexpr int SM_MAIN = 3 * 18432 + 3 * (64 * 152 * 2);   // 113664
    cudaFuncSetAttribute(k_mm<FDIM, FDIM, false, true>,
                         cudaFuncAttributeMaxDynamicSharedMemorySize, SM_WX);
    cudaFuncSetAttribute(k_mm<NROW, LDBM, true, false>,
                         cudaFuncAttributeMaxDynamicSharedMemorySize, SM_MAIN);

    // 0: fp16 operands (X, W, A) + zero s2/counter
    k_prep<<<5377 + 65536, 256>>>(X, A, kern);
    // 1: WX = X16 @ Wt, fused s2 accumulation + last-CTA per-head max
    k_mm<FDIM, FDIM, false, true><<<dim3(4, 64), 256, SM_WX>>>(
        (const __half*)pX16, (const __half*)pWt, (float*)pWX, attn);
    // 2: B build (feats + den cols)
    k_buildB<<<NROW, 256>>>();
    // 3: main fused GEMM (fp16 A, den cols, div+relu epilogue) -> out
    k_mm<NROW, LDBM, true, false><<<dim3(4, 64), 256, SM_MAIN>>>(
        (const __half*)pA16, (const __half*)pB, out, nullptr);
}

// round 11
// speedup vs baseline: 1.1449x; 1.1449x over previous
#include <cuda_runtime.h>
#include <cuda_fp16.h>
#include <cstdint>

#define NROW 8192
#define FDIM 512
#define LDBM 576          // B row stride (halves): 512 feats + 8 den + pad (1152B rows)

#define SWZ(x) ((x) ^ (((x) >> 3) & 0x70))

// ------------------------- scratch -------------------------
__device__ __half   g_X16[(size_t)NROW * FDIM];
__device__ __half   g_Wt [(size_t)FDIM * FDIM];   // Wt[f][c], c=h*64+o
__device__ float    g_WX [(size_t)NROW * FDIM];
__device__ float    g_s2 [8 * NROW];
__device__ float    g_mx [8];
__device__ unsigned g_cnt;
__device__ __half   g_B  [(size_t)NROW * LDBM];   // B[j][c]: w*WX (c<512), w (512..519)

// ------------------------- templated mma.sync GEMM -------------------------
// C[m0+128, n0+BN] = A[M,KLEN] @ B[k][n] (B row stride LDBg halves).
// CONV: A fp32 staged via swizzled smem ring -> fp16 2-slot ring; convert(kt+1)
//       at loop top overlaps compute(kt); A-fragments double-buffered across ks.
// DEN:  8 extra B cols (512..519) accumulated by wn==0 warps; epilogue writes
//       relu(acc/den) straight to C (stride 512).
// S2:   epilogue accumulates s2[h,row] = dot(C_row_tile, a2) via atomicAdd and
//       the LAST CTA computes per-head maxima into g_mx.
template<int KLEN, int LDBg, int BN, bool CONV, bool DEN, bool S2>
__global__ __launch_bounds__(256, CONV ? 1 : 2)
void k_mm(const void* Ag_, const __half* __restrict__ Bg, float* __restrict__ Cg,
          const float* __restrict__ attn)
{
    constexpr int NKT    = KLEN / 32;
    constexpr int BSTR   = (BN == 128) ? 136 : 280;   // halves; conflict-free ldmatrix
    constexpr int NI     = BN / 32;
    constexpr int CPR    = BN / 8 + (DEN ? 1 : 0);    // 16B chunks per B row
    constexpr int A32_SZ = 128 * 32 * 4;              // 16384
    constexpr int A16_SZ = 128 * 40 * 2;              // 10240
    constexpr int B_SZ   = 32 * BSTR * 2;
    constexpr int OFF_A16 = CONV ? 4 * A32_SZ : 0;
    constexpr int OFF_B   = OFF_A16 + (CONV ? 2 : 4) * A16_SZ;

    extern __shared__ char smem[];
    const uint32_t sbase = (uint32_t)__cvta_generic_to_shared(smem);

    const int tid = threadIdx.x;
    const int wid = tid >> 5, lane = tid & 31;
    const int wm = wid & 1, wn = wid >> 1;
    const int lr = lane & 15, lc = (lane >> 4) * 8;
    const int l4 = lane & 3,  lg = lane >> 2;
    const int m0 = blockIdx.y * 128, n0 = blockIdx.x * BN;

    const float*  A32g = (const float*)Ag_;
    const __half* A16g = (const __half*)Ag_;

    float acc[4][NI][4];
    #pragma unroll
    for (int a = 0; a < 4; a++)
        #pragma unroll
        for (int b = 0; b < NI; b++)
            #pragma unroll
            for (int c = 0; c < 4; c++) acc[a][b][c] = 0.f;
    float accD[4][4];
    if (DEN) {
        #pragma unroll
        for (int a = 0; a < 4; a++)
            #pragma unroll
            for (int c = 0; c < 4; c++) accD[a][c] = 0.f;
    }

    auto load_stage = [&](int kt) {
        if (CONV) {
            uint32_t sa = sbase + (kt & 3) * A32_SZ;
            const float* g0 = A32g + (size_t)m0 * KLEN + (size_t)kt * 32;
            #pragma unroll
            for (int i = 0; i < 4; i++) {              // 1024 16B chunks (swizzled)
                int ch = i * 256 + tid;
                int r = ch >> 3, c4 = ch & 7;
                asm volatile("cp.async.cg.shared.global [%0], [%1], 16;"
                             :: "r"(sa + SWZ(r * 128 + c4 * 16)),
                                "l"(g0 + (size_t)r * KLEN + c4 * 4));
            }
        } else {
            uint32_t sa = sbase + OFF_A16 + (kt & 3) * A16_SZ;
            const __half* g0 = A16g + (size_t)m0 * KLEN + (size_t)kt * 32;
            #pragma unroll
            for (int i = 0; i < 2; i++) {
                int ch = i * 256 + tid;
                int r = ch >> 2, c8 = ch & 3;
                asm volatile("cp.async.cg.shared.global [%0], [%1], 16;"
                             :: "r"(sa + r * 80 + c8 * 16),
                                "l"(g0 + (size_t)r * KLEN + c8 * 8));
            }
        }
        uint32_t sb = sbase + OFF_B + (kt & 3) * B_SZ;
        const __half* gb = Bg + (size_t)kt * 32 * LDBg;
        #pragma unroll
        for (int ch = tid; ch < 32 * CPR; ch += 256) {
            int r = ch / CPR, cc = ch % CPR;
            int gcol = (cc < BN / 8) ? (n0 + cc * 8) : 512;
            asm volatile("cp.async.cg.shared.global [%0], [%1], 16;"
                         :: "r"(sb + r * (BSTR * 2) + cc * 16),
                            "l"(gb + (size_t)r * LDBg + gcol));
        }
    };

    auto convert = [&](int kt) {                       // A32[kt&3] -> A16[kt&1]
        const char* s32 = smem + (kt & 3) * A32_SZ;
        const int row = tid >> 1, half = tid & 1;
        const uint32_t rb = row * 128 + half * 64;
        float4 v[4];
        #pragma unroll
        for (int j = 0; j < 4; j++)
            v[j] = *reinterpret_cast<const float4*>(s32 + SWZ(rb + j * 16));
        union { uint4 u; __half2 h[4]; } p0, p1;
        p0.h[0] = __floats2half2_rn(v[0].x, v[0].y);
        p0.h[1] = __floats2half2_rn(v[0].z, v[0].w);
        p0.h[2] = __floats2half2_rn(v[1].x, v[1].y);
        p0.h[3] = __floats2half2_rn(v[1].z, v[1].w);
        p1.h[0] = __floats2half2_rn(v[2].x, v[2].y);
        p1.h[1] = __floats2half2_rn(v[2].z, v[2].w);
        p1.h[2] = __floats2half2_rn(v[3].x, v[3].y);
        p1.h[3] = __floats2half2_rn(v[3].z, v[3].w);
        __half* d = (__half*)(smem + OFF_A16 + (kt & 1) * A16_SZ) + row * 40 + half * 16;
        ((uint4*)d)[0] = p0.u;
        ((uint4*)d)[1] = p1.u;
    };

    // ---- fragment loaders / MMA bundles ----
    auto ldsmA = [&](uint32_t a16b, int ks, uint32_t (*af)[4]) {
        #pragma unroll
        for (int mi = 0; mi < 4; mi++) {
            uint32_t ad = a16b + ((wm * 64 + mi * 16 + lr) * 40 + ks * 16 + lc) * 2;
            asm volatile("ldmatrix.sync.aligned.m8n8.x4.shared.b16 {%0,%1,%2,%3}, [%4];"
                         : "=r"(af[mi][0]), "=r"(af[mi][1]),
                           "=r"(af[mi][2]), "=r"(af[mi][3]) : "r"(ad));
        }
    };
    auto ldsmDn = [&](uint32_t bb, int ks, uint32_t* dn) {
        uint32_t dd = bb + ((ks * 16 + lr) * BSTR + BN) * 2;
        asm volatile("ldmatrix.sync.aligned.m8n8.x2.trans.shared.b16 {%0,%1}, [%2];"
                     : "=r"(dn[0]), "=r"(dn[1]) : "r"(dd));
    };
    auto ldsmB = [&](uint32_t bb, int ks, uint32_t (*bf)[2]) {
        #pragma unroll
        for (int nj = 0; nj < NI / 2; nj++) {
            uint32_t bd_ = bb + ((ks * 16 + lr) * BSTR + wn * (BN / 4) + nj * 16 + lc) * 2;
            asm volatile("ldmatrix.sync.aligned.m8n8.x4.trans.shared.b16 {%0,%1,%2,%3}, [%4];"
                         : "=r"(bf[nj * 2][0]), "=r"(bf[nj * 2][1]),
                           "=r"(bf[nj * 2 + 1][0]), "=r"(bf[nj * 2 + 1][1]) : "r"(bd_));
        }
    };
    auto mmas = [&](uint32_t (*af)[4], uint32_t (*bf)[2], uint32_t* dn) {
        #pragma unroll
        for (int mi = 0; mi < 4; mi++) {
            #pragma unroll
            for (int ni = 0; ni < NI; ni++)
                asm volatile(
                    "mma.sync.aligned.m16n8k16.row.col.f32.f16.f16.f32 "
                    "{%0,%1,%2,%3}, {%4,%5,%6,%7}, {%8,%9}, {%0,%1,%2,%3};"
                    : "+f"(acc[mi][ni][0]), "+f"(acc[mi][ni][1]),
                      "+f"(acc[mi][ni][2]), "+f"(acc[mi][ni][3])
                    : "r"(af[mi][0]), "r"(af[mi][1]), "r"(af[mi][2]), "r"(af[mi][3]),
                      "r"(bf[ni][0]), "r"(bf[ni][1]));
            if (DEN && wn == 0)
                asm volatile(
                    "mma.sync.aligned.m16n8k16.row.col.f32.f16.f16.f32 "
                    "{%0,%1,%2,%3}, {%4,%5,%6,%7}, {%8,%9}, {%0,%1,%2,%3};"
                    : "+f"(accD[mi][0]), "+f"(accD[mi][1]),
                      "+f"(accD[mi][2]), "+f"(accD[mi][3])
                    : "r"(af[mi][0]), "r"(af[mi][1]), "r"(af[mi][2]), "r"(af[mi][3]),
                      "r"(dn[0]), "r"(dn[1]));
        }
    };

    auto compute = [&](int kt) {
        const uint32_t a16b = sbase + OFF_A16 + (CONV ? (kt & 1) : (kt & 3)) * A16_SZ;
        const uint32_t bb   = sbase + OFF_B + (kt & 3) * B_SZ;
        if (CONV) {
            // software-pipelined fragments: A(ks+1)/den(ks+1) prefetch under MMA(ks)
            uint32_t af[2][4][4], dn[2][2], bf[NI][2];
            ldsmA(a16b, 0, af[0]);
            if (DEN && wn == 0) ldsmDn(bb, 0, dn[0]);
            #pragma unroll
            for (int ks = 0; ks < 2; ks++) {
                ldsmB(bb, ks, bf);
                if (ks == 0) {
                    ldsmA(a16b, 1, af[1]);
                    if (DEN && wn == 0) ldsmDn(bb, 1, dn[1]);
                }
                mmas(af[ks], bf, dn[ks]);
            }
        } else {
            uint32_t af[4][4], dn[2], bf[NI][2];
            #pragma unroll
            for (int ks = 0; ks < 2; ks++) {
                ldsmA(a16b, ks, af);
                ldsmB(bb, ks, bf);
                if (DEN && wn == 0) ldsmDn(bb, ks, dn);
                mmas(af, bf, dn);
            }
        }
    };

    // ---- preamble: 3 stages committed; stages 0,1 resident ----
    load_stage(0); asm volatile("cp.async.commit_group;");
    load_stage(1); asm volatile("cp.async.commit_group;");
    load_stage(2); asm volatile("cp.async.commit_group;");
    asm volatile("cp.async.wait_group 1;");
    __syncthreads();
    if (CONV) { convert(0); __syncthreads(); }

    #pragma unroll 1
    for (int kt = 0; kt < NKT; kt++) {
        if (CONV && kt + 1 < NKT) convert(kt + 1);     // overlaps prev tensor drain
        compute(kt);
        if (kt + 3 < NKT) {
            load_stage(kt + 3);
            asm volatile("cp.async.commit_group;");
            asm volatile("cp.async.wait_group 1;");    // in-order retire: <=kt+2 resident
        } else {
            asm volatile("cp.async.wait_group 0;");    // tail drain (exact, no race)
        }
        __syncthreads();
    }

    // ---- epilogue (den scratch overlays stage-0 smem; mainloop fully done) ----
    float* ds = (float*)smem;
    if (DEN) {
        if (wn == 0) {
            #pragma unroll
            for (int mi = 0; mi < 4; mi++) {
                int r = wm * 64 + mi * 16 + lg;
                ds[r * 8 + l4 * 2]           = 1.f / accD[mi][0];
                ds[r * 8 + l4 * 2 + 1]       = 1.f / accD[mi][1];
                ds[(r + 8) * 8 + l4 * 2]     = 1.f / accD[mi][2];
                ds[(r + 8) * 8 + l4 * 2 + 1] = 1.f / accD[mi][3];
            }
        }
        __syncthreads();
    }
    #pragma unroll
    for (int mi = 0; mi < 4; mi++) {
        int rl = wm * 64 + mi * 16 + lg;
        int rg = m0 + rl;
        #pragma unroll
        for (int ni = 0; ni < NI; ni++) {
            int c = n0 + wn * (BN / 4) + ni * 8 + l4 * 2;
            if (DEN) {
                int h = c >> 6;
                float d0 = ds[rl * 8 + h], d1 = ds[(rl + 8) * 8 + h];
                *reinterpret_cast<float2*>(&Cg[(size_t)rg * 512 + c]) =
                    make_float2(fmaxf(acc[mi][ni][0] * d0, 0.f),
                                fmaxf(acc[mi][ni][1] * d0, 0.f));
                *reinterpret_cast<float2*>(&Cg[(size_t)(rg + 8) * 512 + c]) =
                    make_float2(fmaxf(acc[mi][ni][2] * d1, 0.f),
                                fmaxf(acc[mi][ni][3] * d1, 0.f));
            } else {
                *reinterpret_cast<float2*>(&Cg[(size_t)rg * 512 + c]) =
                    make_float2(acc[mi][ni][0], acc[mi][ni][1]);
                *reinterpret_cast<float2*>(&Cg[(size_t)(rg + 8) * 512 + c]) =
                    make_float2(acc[mi][ni][2], acc[mi][ni][3]);
            }
        }
    }
    if (S2) {                                          // fused s2 partial dot
        const int hh = (n0 + wn * 32) >> 6;
        const float* a2 = attn + hh * 128 + 64;
        float a2v[NI][2];
        #pragma unroll
        for (int ni = 0; ni < NI; ni++) {
            int c = (wn * 32 + ni * 8 + l4 * 2) & 63;
            a2v[ni][0] = __ldg(a2 + c);
            a2v[ni][1] = __ldg(a2 + c + 1);
        }
        #pragma unroll
        for (int mi = 0; mi < 4; mi++) {
            float p0 = 0.f, p1 = 0.f;
            #pragma unroll
            for (int ni = 0; ni < NI; ni++) {
                p0 += acc[mi][ni][0] * a2v[ni][0] + acc[mi][ni][1] * a2v[ni][1];
                p1 += acc[mi][ni][2] * a2v[ni][0] + acc[mi][ni][3] * a2v[ni][1];
            }
            p0 += __shfl_xor_sync(0xFFFFFFFFu, p0, 1);
            p0 += __shfl_xor_sync(0xFFFFFFFFu, p0, 2);
            p1 += __shfl_xor_sync(0xFFFFFFFFu, p1, 1);
            p1 += __shfl_xor_sync(0xFFFFFFFFu, p1, 2);
            if (l4 == 0) {
                int r = m0 + wm * 64 + mi * 16 + lg;
                atomicAdd(&g_s2[hh * NROW + r], p0);
                atomicAdd(&g_s2[hh * NROW + r + 8], p1);
            }
        }
        __threadfence();
        __syncthreads();
        __shared__ unsigned sLast;
        if (tid == 0) sLast = (atomicAdd(&g_cnt, 1u) == 255u) ? 1u : 0u;
        __syncthreads();
        if (sLast) {
            __threadfence();
            const float4* p = reinterpret_cast<const float4*>(&g_s2[wid * NROW]);
            float m = -1e30f;
            #pragma unroll 4
            for (int i = lane; i < 2048; i += 32) {
                float4 v = __ldg(p + i);
                m = fmaxf(fmaxf(m, fmaxf(v.x, v.y)), fmaxf(v.z, v.w));
            }
            #pragma unroll
            for (int off = 16; off > 0; off >>= 1)
                m = fmaxf(m, __shfl_xor_sync(0xFFFFFFFFu, m, off));
            if (lane == 0) g_mx[wid] = m;
        }
    }
}

// ------------------------- prep / small kernels -------------------------
__global__ void k_prep(const float* __restrict__ X, const float* __restrict__ kern) {
    int b = blockIdx.x;
    if (b < 4096) {                                    // X -> fp16
        size_t i = (size_t)b * 256 + threadIdx.x;
        float4 v = reinterpret_cast<const float4*>(X)[i];
        __half2* d = reinterpret_cast<__half2*>(g_X16);
        d[2 * i]     = __floats2half2_rn(v.x, v.y);
        d[2 * i + 1] = __floats2half2_rn(v.z, v.w);
    } else if (b < 5120) {                             // kernels -> Wt[f][c]
        size_t i = (size_t)(b - 4096) * 256 + threadIdx.x;
        int f = (int)(i >> 9), c = (int)(i & 511);
        g_Wt[i] = __float2half_rn(kern[((size_t)(c >> 6) * 512 + f) * 64 + (c & 63)]);
    } else if (b < 5376) {                             // zero s2 (graph-replay safe)
        g_s2[(b - 5120) * 256 + threadIdx.x] = 0.f;
    } else {
        if (threadIdx.x == 0) g_cnt = 0u;
    }
}

__global__ void k_buildB() {                           // grid 8192, block 256
    int n = blockIdx.x;
    int c2 = threadIdx.x;                              // cols 2*c2, 2*c2+1 (same head)
    int h = c2 >> 5;
    float w = __expf(g_s2[h * NROW + n] - g_mx[h]);
    float2 wx = *reinterpret_cast<const float2*>(&g_WX[(size_t)n * FDIM + 2 * c2]);
    *reinterpret_cast<__half2*>(&g_B[(size_t)n * LDBM + 2 * c2]) =
        __floats2half2_rn(w * wx.x, w * wx.y);
    if (c2 < 8) {                                      // den col for head c2
        float wd = __expf(g_s2[c2 * NROW + n] - g_mx[c2]);
        g_B[(size_t)n * LDBM + 512 + c2] = __float2half_rn(wd);
    }
}

// ------------------------- launcher -------------------------
extern "C" void kernel_launch(void* const* d_in, const int* in_sizes, int n_in,
                              void* d_out, int out_size)
{
    const float* X    = (const float*)d_in[0];
    const float* A    = (const float*)d_in[1];
    const float* kern = (const float*)d_in[2];
    const float* attn = (const float*)d_in[3];
    float* out = (float*)d_out;

    void *pX16, *pWt, *pWX, *pB;
    cudaGetSymbolAddress(&pX16, g_X16);
    cudaGetSymbolAddress(&pWt,  g_Wt);
    cudaGetSymbolAddress(&pWX,  g_WX);
    cudaGetSymbolAddress(&pB,   g_B);

    constexpr int SM_WX   = 4 * 10240 + 4 * (32 * 136 * 2);                    // 75776
    constexpr int SM_MAIN = 4 * 16384 + 2 * 10240 + 4 * (32 * 280 * 2);        // 157696
    cudaFuncSetAttribute(k_mm<FDIM, FDIM, 128, false, false, true>,
                         cudaFuncAttributeMaxDynamicSharedMemorySize, SM_WX);
    cudaFuncSetAttribute(k_mm<NROW, LDBM, 256, true, true, false>,
                         cudaFuncAttributeMaxDynamicSharedMemorySize, SM_MAIN);

    // 0: fp16 operands (X, W) + zero s2/counter
    k_prep<<<5377, 256>>>(X, kern);
    // 1: WX = X16 @ Wt, fused s2 accumulation + last-CTA per-head max
    k_mm<FDIM, FDIM, 128, false, false, true><<<dim3(4, 64), 256, SM_WX>>>(
        pX16, (const __half*)pWt, (float*)pWX, attn);
    // 2: B build (feats + den cols)
    k_buildB<<<NROW, 256>>>();
    // 3: main fused GEMM (inline A conversion, pipelined fragments,
    //    den cols, div+relu epilogue) -> out
    k_mm<NROW, LDBM, 256, true, true, false><<<dim3(2, 64), 256, SM_MAIN>>>(
        A, (const __half*)pB, out, nullptr);
}

// round 12
// speedup vs baseline: 1.3377x; 1.1684x over previous
#include <cuda_runtime.h>
#include <cuda_fp16.h>
#include <cstdint>

#define NROW 8192
#define FDIM 512
#define LDBM 576          // B row stride (halves): 512 feats + 8 den + pad (1152B rows)

#define SWZ(x) ((x) ^ (((x) >> 3) & 0x70))

// ------------------------- scratch -------------------------
__device__ __half   g_X16[(size_t)NROW * FDIM];
__device__ __half   g_Wt [(size_t)FDIM * FDIM];   // Wt[f][c], c=h*64+o
__device__ float    g_WX [(size_t)NROW * FDIM];
__device__ float    g_s2 [8 * NROW];
__device__ float    g_mx [8];
__device__ unsigned g_cnt;
__device__ __half   g_B  [(size_t)NROW * LDBM];   // B[j][c]: w*WX (c<512), w (512..519)

// ------------------------- templated mma.sync GEMM (4 warps, 2x2 grid) ------
// C[m0+128, n0+128] = A[M,KLEN] @ B[k][n] (B row stride LDBg halves).
// 128 threads; warp (wm,wn) in 2x2 owns a 64x64 tile -> minimal ldmatrix dup.
// CONV: A fp32 staged via swizzled 3-slot smem ring -> 2-slot fp16 ring.
// DEN:  8 extra B cols (512..519) accumulated by wn==0 warps; epilogue writes
//       relu(acc/den) straight to C (stride 512).
// S2:   epilogue accumulates s2[h,row] = dot(C_row_tile, a2) via atomicAdd and
//       the LAST CTA computes per-head maxima into g_mx.
template<int KLEN, int LDBg, bool CONV, bool DEN, bool S2>
__global__ __launch_bounds__(128, 2)
void k_mm(const void* Ag_, const __half* __restrict__ Bg, float* __restrict__ Cg,
          const float* __restrict__ attn)
{
    constexpr int NKT    = KLEN / 32;
    constexpr int BSTR   = DEN ? 152 : 136;       // halves; conflict-free ldmatrix
    constexpr int NI     = 8;                     // 64 warp cols / 8
    constexpr int CPR    = 16 + (DEN ? 1 : 0);    // 16B chunks per B row
    constexpr int A32_SZ = 128 * 32 * 4;          // 16384
    constexpr int A16_SZ = 128 * 40 * 2;          // 10240
    constexpr int B_SZ   = 32 * BSTR * 2;
    constexpr int NSTG   = CONV ? 3 : 4;          // B (and A) ring depth
    constexpr int OFF_A16 = CONV ? 3 * A32_SZ : 0;
    constexpr int OFF_B   = OFF_A16 + (CONV ? 2 : 4) * A16_SZ;

    extern __shared__ char smem[];
    const uint32_t sbase = (uint32_t)__cvta_generic_to_shared(smem);

    const int tid = threadIdx.x;
    const int wid = tid >> 5, lane = tid & 31;
    const int wm = wid & 1, wn = wid >> 1;        // 2x2 warp grid
    const int lr = lane & 15, lc = (lane >> 4) * 8;
    const int l4 = lane & 3,  lg = lane >> 2;
    const int m0 = blockIdx.y * 128, n0 = blockIdx.x * 128;

    const float*  A32g = (const float*)Ag_;
    const __half* A16g = (const __half*)Ag_;

    float acc[4][NI][4];
    #pragma unroll
    for (int a = 0; a < 4; a++)
        #pragma unroll
        for (int b = 0; b < NI; b++)
            #pragma unroll
            for (int c = 0; c < 4; c++) acc[a][b][c] = 0.f;
    float accD[4][4];
    if (DEN) {
        #pragma unroll
        for (int a = 0; a < 4; a++)
            #pragma unroll
            for (int c = 0; c < 4; c++) accD[a][c] = 0.f;
    }

    auto load_stage = [&](int kt) {
        const int s = CONV ? (kt % 3) : (kt & 3);
        if (CONV) {
            uint32_t sa = sbase + s * A32_SZ;
            const float* g0 = A32g + (size_t)m0 * KLEN + (size_t)kt * 32;
            #pragma unroll
            for (int i = 0; i < 8; i++) {             // 1024 16B chunks (swizzled)
                int ch = i * 128 + tid;
                int r = ch >> 3, c4 = ch & 7;
                asm volatile("cp.async.cg.shared.global [%0], [%1], 16;"
                             :: "r"(sa + SWZ(r * 128 + c4 * 16)),
                                "l"(g0 + (size_t)r * KLEN + c4 * 4));
            }
        } else {
            uint32_t sa = sbase + OFF_A16 + s * A16_SZ;
            const __half* g0 = A16g + (size_t)m0 * KLEN + (size_t)kt * 32;
            #pragma unroll
            for (int i = 0; i < 4; i++) {             // 512 16B chunks
                int ch = i * 128 + tid;
                int r = ch >> 2, c8 = ch & 3;
                asm volatile("cp.async.cg.shared.global [%0], [%1], 16;"
                             :: "r"(sa + r * 80 + c8 * 16),
                                "l"(g0 + (size_t)r * KLEN + c8 * 8));
            }
        }
        uint32_t sb = sbase + OFF_B + s * B_SZ;
        const __half* gb = Bg + (size_t)kt * 32 * LDBg;
        #pragma unroll
        for (int ch = tid; ch < 32 * CPR; ch += 128) {
            int r = ch / CPR, cc = ch % CPR;
            int gcol = (cc < 16) ? (n0 + cc * 8) : 512;
            asm volatile("cp.async.cg.shared.global [%0], [%1], 16;"
                         :: "r"(sb + r * (BSTR * 2) + cc * 16),
                            "l"(gb + (size_t)r * LDBg + gcol));
        }
    };

    auto convert = [&](int kt) {                      // A32[kt%3] -> A16[kt&1]
        const char* s32 = smem + (kt % 3) * A32_SZ;
        const int row = tid;                          // 128 threads = 128 rows
        float4 v[8];
        #pragma unroll
        for (int j = 0; j < 8; j++)
            v[j] = *reinterpret_cast<const float4*>(s32 + SWZ(row * 128 + j * 16));
        __half* d = (__half*)(smem + OFF_A16 + (kt & 1) * A16_SZ) + row * 40;
        #pragma unroll
        for (int j2 = 0; j2 < 4; j2++) {
            union { uint4 u; __half2 h[4]; } p;
            p.h[0] = __floats2half2_rn(v[2 * j2].x, v[2 * j2].y);
            p.h[1] = __floats2half2_rn(v[2 * j2].z, v[2 * j2].w);
            p.h[2] = __floats2half2_rn(v[2 * j2 + 1].x, v[2 * j2 + 1].y);
            p.h[3] = __floats2half2_rn(v[2 * j2 + 1].z, v[2 * j2 + 1].w);
            *reinterpret_cast<uint4*>(d + j2 * 8) = p.u;
        }
    };

    auto compute = [&](int kt) {
        const uint32_t a16b = sbase + OFF_A16 + (CONV ? (kt & 1) : (kt & 3)) * A16_SZ;
        const uint32_t bb   = sbase + OFF_B + (CONV ? (kt % 3) : (kt & 3)) * B_SZ;
        #pragma unroll
        for (int ks = 0; ks < 2; ks++) {
            uint32_t af[4][4], bf[NI][2], dn[2];
            #pragma unroll
            for (int mi = 0; mi < 4; mi++) {
                uint32_t ad = a16b + ((wm * 64 + mi * 16 + lr) * 40 + ks * 16 + lc) * 2;
                asm volatile("ldmatrix.sync.aligned.m8n8.x4.shared.b16 {%0,%1,%2,%3}, [%4];"
                             : "=r"(af[mi][0]), "=r"(af[mi][1]),
                               "=r"(af[mi][2]), "=r"(af[mi][3]) : "r"(ad));
            }
            #pragma unroll
            for (int nj = 0; nj < 4; nj++) {
                uint32_t bd_ = bb + ((ks * 16 + lr) * BSTR + wn * 64 + nj * 16 + lc) * 2;
                asm volatile("ldmatrix.sync.aligned.m8n8.x4.trans.shared.b16 {%0,%1,%2,%3}, [%4];"
                             : "=r"(bf[nj * 2][0]), "=r"(bf[nj * 2][1]),
                               "=r"(bf[nj * 2 + 1][0]), "=r"(bf[nj * 2 + 1][1]) : "r"(bd_));
            }
            if (DEN && wn == 0) {
                uint32_t dd = bb + ((ks * 16 + lr) * BSTR + 128) * 2;
                asm volatile("ldmatrix.sync.aligned.m8n8.x2.trans.shared.b16 {%0,%1}, [%2];"
                             : "=r"(dn[0]), "=r"(dn[1]) : "r"(dd));
            }
            #pragma unroll
            for (int mi = 0; mi < 4; mi++) {
                #pragma unroll
                for (int ni = 0; ni < NI; ni++)
                    asm volatile(
                        "mma.sync.aligned.m16n8k16.row.col.f32.f16.f16.f32 "
                        "{%0,%1,%2,%3}, {%4,%5,%6,%7}, {%8,%9}, {%0,%1,%2,%3};"
                        : "+f"(acc[mi][ni][0]), "+f"(acc[mi][ni][1]),
                          "+f"(acc[mi][ni][2]), "+f"(acc[mi][ni][3])
                        : "r"(af[mi][0]), "r"(af[mi][1]), "r"(af[mi][2]), "r"(af[mi][3]),
                          "r"(bf[ni][0]), "r"(bf[ni][1]));
                if (DEN && wn == 0)
                    asm volatile(
                        "mma.sync.aligned.m16n8k16.row.col.f32.f16.f16.f32 "
                        "{%0,%1,%2,%3}, {%4,%5,%6,%7}, {%8,%9}, {%0,%1,%2,%3};"
                        : "+f"(accD[mi][0]), "+f"(accD[mi][1]),
                          "+f"(accD[mi][2]), "+f"(accD[mi][3])
                        : "r"(af[mi][0]), "r"(af[mi][1]), "r"(af[mi][2]), "r"(af[mi][3]),
                          "r"(dn[0]), "r"(dn[1]));
            }
        }
    };

    // ---- preamble ----
    if (CONV) {
        load_stage(0); asm volatile("cp.async.commit_group;");
        load_stage(1); asm volatile("cp.async.commit_group;");
        asm volatile("cp.async.wait_group 1;");       // stage 0 resident
        __syncthreads();
        convert(0);
        __syncthreads();
    } else {
        load_stage(0); asm volatile("cp.async.commit_group;");
        load_stage(1); asm volatile("cp.async.commit_group;");
        load_stage(2); asm volatile("cp.async.commit_group;");
        asm volatile("cp.async.wait_group 2;");       // stage 0 resident
        __syncthreads();
    }

    // ---- mainloop: unconditional commits keep wait accounting exact ----
    #pragma unroll 1
    for (int kt = 0; kt < NKT; kt++) {
        compute(kt);
        if (CONV) {
            if (kt + 2 < NKT) load_stage(kt + 2);
            asm volatile("cp.async.commit_group;");
            asm volatile("cp.async.wait_group 1;");   // stage kt+1 resident
        } else {
            if (kt + 3 < NKT) load_stage(kt + 3);
            asm volatile("cp.async.commit_group;");
            asm volatile("cp.async.wait_group 2;");   // stage kt+1 resident
        }
        __syncthreads();
        if (CONV && kt + 1 < NKT) {
            convert(kt + 1);
            __syncthreads();
        }
    }

    // ---- epilogue (scratch overlays stage-0 smem; mainloop fully done) ----
    float* ds = (float*)smem;
    if (DEN) {
        if (wn == 0) {
            #pragma unroll
            for (int mi = 0; mi < 4; mi++) {
                int r = wm * 64 + mi * 16 + lg;
                ds[r * 8 + l4 * 2]           = 1.f / accD[mi][0];
                ds[r * 8 + l4 * 2 + 1]       = 1.f / accD[mi][1];
                ds[(r + 8) * 8 + l4 * 2]     = 1.f / accD[mi][2];
                ds[(r + 8) * 8 + l4 * 2 + 1] = 1.f / accD[mi][3];
            }
        }
        __syncthreads();
    }
    #pragma unroll
    for (int mi = 0; mi < 4; mi++) {
        int rl = wm * 64 + mi * 16 + lg;
        int rg = m0 + rl;
        #pragma unroll
        for (int ni = 0; ni < NI; ni++) {
            int c = n0 + wn * 64 + ni * 8 + l4 * 2;
            if (DEN) {
                int h = c >> 6;
                float d0 = ds[rl * 8 + h], d1 = ds[(rl + 8) * 8 + h];
                *reinterpret_cast<float2*>(&Cg[(size_t)rg * 512 + c]) =
                    make_float2(fmaxf(acc[mi][ni][0] * d0, 0.f),
                                fmaxf(acc[mi][ni][1] * d0, 0.f));
                *reinterpret_cast<float2*>(&Cg[(size_t)(rg + 8) * 512 + c]) =
                    make_float2(fmaxf(acc[mi][ni][2] * d1, 0.f),
                                fmaxf(acc[mi][ni][3] * d1, 0.f));
            } else {
                *reinterpret_cast<float2*>(&Cg[(size_t)rg * 512 + c]) =
                    make_float2(acc[mi][ni][0], acc[mi][ni][1]);
                *reinterpret_cast<float2*>(&Cg[(size_t)(rg + 8) * 512 + c]) =
                    make_float2(acc[mi][ni][2], acc[mi][ni][3]);
            }
        }
    }
    if (S2) {                                         // fused s2 partial dot
        const int hh = (n0 >> 6) + wn;                // warp covers exactly 1 head
        const float* a2 = attn + hh * 128 + 64;
        float a2v[NI][2];
        #pragma unroll
        for (int ni = 0; ni < NI; ni++) {
            int c = ni * 8 + l4 * 2;
            a2v[ni][0] = __ldg(a2 + c);
            a2v[ni][1] = __ldg(a2 + c + 1);
        }
        #pragma unroll
        for (int mi = 0; mi < 4; mi++) {
            float p0 = 0.f, p1 = 0.f;
            #pragma unroll
            for (int ni = 0; ni < NI; ni++) {
                p0 += acc[mi][ni][0] * a2v[ni][0] + acc[mi][ni][1] * a2v[ni][1];
                p1 += acc[mi][ni][2] * a2v[ni][0] + acc[mi][ni][3] * a2v[ni][1];
            }
            p0 += __shfl_xor_sync(0xFFFFFFFFu, p0, 1);
            p0 += __shfl_xor_sync(0xFFFFFFFFu, p0, 2);
            p1 += __shfl_xor_sync(0xFFFFFFFFu, p1, 1);
            p1 += __shfl_xor_sync(0xFFFFFFFFu, p1, 2);
            if (l4 == 0) {
                int r = m0 + wm * 64 + mi * 16 + lg;
                atomicAdd(&g_s2[hh * NROW + r], p0);
                atomicAdd(&g_s2[hh * NROW + r + 8], p1);
            }
        }
        __threadfence();
        __syncthreads();
        __shared__ unsigned sLast;
        if (tid == 0) sLast = (atomicAdd(&g_cnt, 1u) == 255u) ? 1u : 0u;
        __syncthreads();
        if (sLast) {
            __threadfence();
            #pragma unroll
            for (int h = wid; h < 8; h += 4) {        // 4 warps cover 8 heads
                const float4* p = reinterpret_cast<const float4*>(&g_s2[h * NROW]);
                float m = -1e30f;
                #pragma unroll 4
                for (int i = lane; i < 2048; i += 32) {
                    float4 v = __ldg(p + i);
                    m = fmaxf(fmaxf(m, fmaxf(v.x, v.y)), fmaxf(v.z, v.w));
                }
                #pragma unroll
                for (int off = 16; off > 0; off >>= 1)
                    m = fmaxf(m, __shfl_xor_sync(0xFFFFFFFFu, m, off));
                if (lane == 0) g_mx[h] = m;
            }
        }
    }
}

// ------------------------- prep / small kernels -------------------------
__global__ void k_prep(const float* __restrict__ X, const float* __restrict__ kern) {
    int b = blockIdx.x;
    if (b < 4096) {                                   // X -> fp16
        size_t i = (size_t)b * 256 + threadIdx.x;
        float4 v = reinterpret_cast<const float4*>(X)[i];
        __half2* d = reinterpret_cast<__half2*>(g_X16);
        d[2 * i]     = __floats2half2_rn(v.x, v.y);
        d[2 * i + 1] = __floats2half2_rn(v.z, v.w);
    } else if (b < 5120) {                            // kernels -> Wt[f][c]
        size_t i = (size_t)(b - 4096) * 256 + threadIdx.x;
        int f = (int)(i >> 9), c = (int)(i & 511);
        g_Wt[i] = __float2half_rn(kern[((size_t)(c >> 6) * 512 + f) * 64 + (c & 63)]);
    } else if (b < 5376) {                            // zero s2 (graph-replay safe)
        g_s2[(b - 5120) * 256 + threadIdx.x] = 0.f;
    } else {
        if (threadIdx.x == 0) g_cnt = 0u;
    }
}

__global__ void k_buildB() {                          // grid 8192, block 256
    int n = blockIdx.x;
    int c2 = threadIdx.x;                             // cols 2*c2, 2*c2+1 (same head)
    int h = c2 >> 5;
    float w = __expf(g_s2[h * NROW + n] - g_mx[h]);
    float2 wx = *reinterpret_cast<const float2*>(&g_WX[(size_t)n * FDIM + 2 * c2]);
    *reinterpret_cast<__half2*>(&g_B[(size_t)n * LDBM + 2 * c2]) =
        __floats2half2_rn(w * wx.x, w * wx.y);
    if (c2 < 8) {                                     // den col for head c2
        float wd = __expf(g_s2[c2 * NROW + n] - g_mx[c2]);
        g_B[(size_t)n * LDBM + 512 + c2] = __float2half_rn(wd);
    }
}

// ------------------------- launcher -------------------------
extern "C" void kernel_launch(void* const* d_in, const int* in_sizes, int n_in,
                              void* d_out, int out_size)
{
    const float* X    = (const float*)d_in[0];
    const float* A    = (const float*)d_in[1];
    const float* kern = (const float*)d_in[2];
    const float* attn = (const float*)d_in[3];
    float* out = (float*)d_out;

    void *pX16, *pWt, *pWX, *pB;
    cudaGetSymbolAddress(&pX16, g_X16);
    cudaGetSymbolAddress(&pWt,  g_Wt);
    cudaGetSymbolAddress(&pWX,  g_WX);
    cudaGetSymbolAddress(&pB,   g_B);

    constexpr int SM_WX   = 4 * 10240 + 4 * (32 * 136 * 2);               // 75776
    constexpr int SM_MAIN = 3 * 16384 + 2 * 10240 + 3 * (32 * 152 * 2);   // 98816
    cudaFuncSetAttribute(k_mm<FDIM, FDIM, false, false, true>,
                         cudaFuncAttributeMaxDynamicSharedMemorySize, SM_WX);
    cudaFuncSetAttribute(k_mm<NROW, LDBM, true, true, false>,
                         cudaFuncAttributeMaxDynamicSharedMemorySize, SM_MAIN);

    // 0: fp16 operands (X, W) + zero s2/counter
    k_prep<<<5377, 256>>>(X, kern);
    // 1: WX = X16 @ Wt, fused s2 accumulation + last-CTA per-head max
    k_mm<FDIM, FDIM, false, false, true><<<dim3(4, 64), 128, SM_WX>>>(
        pX16, (const __half*)pWt, (float*)pWX, attn);
    // 2: B build (feats + den cols)
    k_buildB<<<NROW, 256>>>();
    // 3: main fused GEMM (inline A conversion, 4-warp 2x2 grid, 2 CTAs/SM,
    //    den cols, div+relu epilogue) -> out
    k_mm<NROW, LDBM, true, true, false><<<dim3(4, 64), 128, SM_MAIN>>>(
        A, (const __half*)pB, out, nullptr);
}